// round 5
// baseline (speedup 1.0000x reference)
#include <cuda_runtime.h>
#include <math.h>

#define BB 2
#define SS 2048
#define DD 512
#define HH 8
#define DK 64
#define M_TOTAL (BB*SS)   // 4096

// Scratch (allocation-free)
__device__ float g_Q[BB*HH*SS*DK];
__device__ float g_K[BB*HH*SS*DK];
__device__ float g_V[BB*HH*SS*DK];
__device__ float g_attn[BB*SS*DD];

// ---------------------------------------------------------------------------
__device__ __forceinline__ unsigned f2t(float x) {
    unsigned r;
    asm("cvt.rna.tf32.f32 %0, %1;" : "=r"(r) : "f"(x));
    return r;
}

__device__ __forceinline__ void mma8(float* c,
                                     unsigned a0, unsigned a1, unsigned a2, unsigned a3,
                                     unsigned b0, unsigned b1) {
    asm volatile(
        "mma.sync.aligned.m16n8k8.row.col.f32.tf32.tf32.f32 "
        "{%0,%1,%2,%3}, {%4,%5,%6,%7}, {%8,%9}, {%0,%1,%2,%3};"
        : "+f"(c[0]), "+f"(c[1]), "+f"(c[2]), "+f"(c[3])
        : "r"(a0), "r"(a1), "r"(a2), "r"(a3), "r"(b0), "r"(b1));
}

// ---------------------------------------------------------------------------
// 3xTF32 GEMM body, on-the-fly hi/lo split, permuted-pair smem layout.
// C[M,N] = (A[M,K] @ W[N,K]^T + bias[N]) * alpha.
// Block 128x64, BK=32, 8 warps (4x2). Pitch 40 (LDS.64 conflict-free).
// k-permutation within each 8-group: m<4 -> 2m ; m>=4 -> 2(m-4)+1
// MODE 0: row-major [M,N].  MODE 1: head-split [B,H,S,DK].
// ---------------------------------------------------------------------------
#define PPITCH 40

template<int MODE>
__device__ __forceinline__
void proj_body(const float* __restrict__ A, const float* __restrict__ W,
               const float* __restrict__ bias, float* __restrict__ C,
               float alpha, int m0, int n0, unsigned* sh) {
    unsigned (*Ab)[PPITCH] = (unsigned(*)[PPITCH])sh;                              // 128 rows
    unsigned (*Al)[PPITCH] = (unsigned(*)[PPITCH])(sh + 128*PPITCH);               // 128 rows
    unsigned (*Bb)[PPITCH] = (unsigned(*)[PPITCH])(sh + 2*128*PPITCH);             // 64 rows
    unsigned (*Bl)[PPITCH] = (unsigned(*)[PPITCH])(sh + 2*128*PPITCH + 64*PPITCH); // 64 rows

    const int tid  = threadIdx.x;
    const int lane = tid & 31;
    const int warp = tid >> 5;
    const int g = lane >> 2, c = lane & 3;
    const int wm = warp & 3, wn = warp >> 2;

    float acc[2][4][4] = {};

    for (int kt = 0; kt < 512; kt += 32) {
        __syncthreads();
        // A (128x32) split + permuted store
        #pragma unroll
        for (int i = 0; i < 4; i++) {
            const int f = tid + i * 256;          // 0..1023
            const int r = f >> 3;
            const int colbase = (f & 7) * 4;
            const int base8 = colbase & ~7;
            const int off = (colbase & 4) ? 1 : 0;
            float4 v = *(const float4*)(A + (size_t)(m0 + r) * 512 + kt + colbase);
            float vv[4] = {v.x, v.y, v.z, v.w};
            #pragma unroll
            for (int j = 0; j < 4; j++) {
                unsigned hb = f2t(vv[j]);
                Ab[r][base8 + off + 2*j] = hb;
                Al[r][base8 + off + 2*j] = f2t(vv[j] - __uint_as_float(hb));
            }
        }
        // W (64x32)
        #pragma unroll
        for (int i = 0; i < 2; i++) {
            const int f = tid + i * 256;          // 0..511
            const int r = f >> 3;
            const int colbase = (f & 7) * 4;
            const int base8 = colbase & ~7;
            const int off = (colbase & 4) ? 1 : 0;
            float4 v = *(const float4*)(W + (size_t)(n0 + r) * 512 + kt + colbase);
            float vv[4] = {v.x, v.y, v.z, v.w};
            #pragma unroll
            for (int j = 0; j < 4; j++) {
                unsigned hb = f2t(vv[j]);
                Bb[r][base8 + off + 2*j] = hb;
                Bl[r][base8 + off + 2*j] = f2t(vv[j] - __uint_as_float(hb));
            }
        }
        __syncthreads();

        #pragma unroll
        for (int d = 0; d < 4; d++) {
            const int kc = d * 8 + 2 * c;
            uint2 h0[2], h1[2], l0[2], l1[2];
            #pragma unroll
            for (int mi = 0; mi < 2; mi++) {
                const int rb = wm * 32 + mi * 16;
                h0[mi] = *(const uint2*)&Ab[rb + g][kc];      // a0,a2
                h1[mi] = *(const uint2*)&Ab[rb + g + 8][kc];  // a1,a3
                l0[mi] = *(const uint2*)&Al[rb + g][kc];
                l1[mi] = *(const uint2*)&Al[rb + g + 8][kc];
            }
            uint2 bh[4], bl[4];
            #pragma unroll
            for (int ni = 0; ni < 4; ni++) {
                const int cb = wn * 32 + ni * 8;
                bh[ni] = *(const uint2*)&Bb[cb + g][kc];
                bl[ni] = *(const uint2*)&Bl[cb + g][kc];
            }
            #pragma unroll
            for (int mi = 0; mi < 2; mi++)
                #pragma unroll
                for (int ni = 0; ni < 4; ni++) {
                    mma8(acc[mi][ni], h0[mi].x, h1[mi].x, h0[mi].y, h1[mi].y, bh[ni].x, bh[ni].y);
                    mma8(acc[mi][ni], h0[mi].x, h1[mi].x, h0[mi].y, h1[mi].y, bl[ni].x, bl[ni].y);
                    mma8(acc[mi][ni], l0[mi].x, l1[mi].x, l0[mi].y, l1[mi].y, bh[ni].x, bh[ni].y);
                }
        }
    }

    #pragma unroll
    for (int mi = 0; mi < 2; mi++) {
        const int r0 = m0 + wm * 32 + mi * 16 + g;
        #pragma unroll
        for (int ni = 0; ni < 4; ni++) {
            const int cc = n0 + wn * 32 + ni * 8 + c * 2;
            const float b0 = bias[cc], b1 = bias[cc + 1];
            float v[4];
            v[0] = (acc[mi][ni][0] + b0) * alpha;
            v[1] = (acc[mi][ni][1] + b1) * alpha;
            v[2] = (acc[mi][ni][2] + b0) * alpha;
            v[3] = (acc[mi][ni][3] + b1) * alpha;
            #pragma unroll
            for (int p = 0; p < 2; p++) {
                const int m = r0 + p * 8;
                #pragma unroll
                for (int q = 0; q < 2; q++) {
                    const int n = cc + q;
                    const float val = v[p * 2 + q];
                    if (MODE == 0) {
                        C[(size_t)m * 512 + n] = val;
                    } else {
                        const int b_ = m >> 11, s_ = m & 2047;
                        const int h_ = n >> 6, dk = n & 63;
                        C[(((size_t)(b_ * HH + h_)) * SS + s_) * DK + dk] = val;
                    }
                }
            }
        }
    }
}

// Fused Q/K/V projection: blockIdx.z selects weight/bias/output.
__global__ __launch_bounds__(256, 2)
void qkv_proj_kernel(const float* __restrict__ x,
                     const float* __restrict__ Wq, const float* __restrict__ bq,
                     const float* __restrict__ Wk, const float* __restrict__ bk,
                     const float* __restrict__ Wv, const float* __restrict__ bv) {
    extern __shared__ unsigned sh[];
    const int z = blockIdx.z;
    const float* W    = (z == 0) ? Wq : (z == 1) ? Wk : Wv;
    const float* bias = (z == 0) ? bq : (z == 1) ? bk : bv;
    float* C = (z == 0) ? g_Q : (z == 1) ? g_K : g_V;
    const float alpha = (z == 0) ? 0.125f : 1.0f;
    proj_body<1>(x, W, bias, C, alpha, blockIdx.y * 128, blockIdx.x * 64, sh);
}

__global__ __launch_bounds__(256, 2)
void out_proj_kernel(const float* __restrict__ Wo, const float* __restrict__ bo,
                     float* __restrict__ out) {
    extern __shared__ unsigned sh[];
    proj_body<0>(g_attn, Wo, bo, out, 1.0f, blockIdx.y * 128, blockIdx.x * 64, sh);
}

// ---------------------------------------------------------------------------
// Flash attention, tf32 mma, permuted-pair smem, V transposed.
// Block = 128 q-rows, 8 warps (16 rows each), kv streamed in 64-chunks.
// Pitch 72 -> LDS.64 fragment loads conflict-free. 2 CTAs/SM.
// ---------------------------------------------------------------------------
#define APITCH 72

__global__ __launch_bounds__(256, 2)
void attn_kernel(const float* __restrict__ Q, const float* __restrict__ K,
                 const float* __restrict__ V, float* __restrict__ Out) {
    extern __shared__ unsigned sh[];
    unsigned (*Qs)[APITCH] = (unsigned(*)[APITCH])sh;                  // 128 rows
    unsigned (*Ks)[APITCH] = (unsigned(*)[APITCH])(sh + 128*APITCH);   // 64 rows
    unsigned (*Vt)[APITCH] = (unsigned(*)[APITCH])(sh + 192*APITCH);   // 64 rows ([dk][kv])
    unsigned (*Ps)[APITCH] = (unsigned(*)[APITCH])(sh + 256*APITCH);   // 128 rows

    const int tid  = threadIdx.x;
    const int lane = tid & 31;
    const int warp = tid >> 5;
    const int g = lane >> 2, c = lane & 3;
    const int wr = warp * 16;
    const int qt = blockIdx.x;    // 0..15
    const int bh = blockIdx.y;    // 0..15

    const float* Qb = Q + (size_t)bh * SS * DK + (size_t)qt * 128 * DK;
    const float* Kb = K + (size_t)bh * SS * DK;
    const float* Vb = V + (size_t)bh * SS * DK;

    // Q tile -> permuted tf32 smem
    #pragma unroll
    for (int i = 0; i < 8; i++) {
        const int f = tid + i * 256;
        const int r = f >> 4;
        const int colbase = (f & 15) * 4;
        const int base8 = colbase & ~7;
        const int off = (colbase & 4) ? 1 : 0;
        float4 v = *(const float4*)(Qb + r * 64 + colbase);
        Qs[r][base8 + off]     = f2t(v.x);
        Qs[r][base8 + off + 2] = f2t(v.y);
        Qs[r][base8 + off + 4] = f2t(v.z);
        Qs[r][base8 + off + 6] = f2t(v.w);
    }

    float O[8][4] = {};
    float m0r = -1e30f, m1r = -1e30f, l0 = 0.f, l1 = 0.f;

    for (int kt = 0; kt < 32; kt++) {
        __syncthreads();
        // K: row layout, permuted dk columns
        #pragma unroll
        for (int i = 0; i < 4; i++) {
            const int f = tid + i * 256;
            const int r = f >> 4;
            const int colbase = (f & 15) * 4;
            const int base8 = colbase & ~7;
            const int off = (colbase & 4) ? 1 : 0;
            float4 kv = *(const float4*)(Kb + (size_t)(kt * 64 + r) * 64 + colbase);
            Ks[r][base8 + off]     = f2t(kv.x);
            Ks[r][base8 + off + 2] = f2t(kv.y);
            Ks[r][base8 + off + 4] = f2t(kv.z);
            Ks[r][base8 + off + 6] = f2t(kv.w);
        }
        // V: transposed store Vt[dk][perm(kvrow)]
        #pragma unroll
        for (int i = 0; i < 4; i++) {
            const int f = tid + i * 256;
            const int r = f & 63;               // kv row (32 consecutive per warp)
            const int colbase = (f >> 6) * 4;   // dk
            const int m = r & 7;
            const int pr = (r & ~7) + ((m < 4) ? 2 * m : 2 * (m - 4) + 1);
            float4 vv = *(const float4*)(Vb + (size_t)(kt * 64 + r) * 64 + colbase);
            Vt[colbase][pr]     = f2t(vv.x);
            Vt[colbase + 1][pr] = f2t(vv.y);
            Vt[colbase + 2][pr] = f2t(vv.z);
            Vt[colbase + 3][pr] = f2t(vv.w);
        }
        __syncthreads();

        // S = Q K^T
        float sc[8][4] = {};
        #pragma unroll
        for (int d = 0; d < 8; d++) {
            const int kc = d * 8 + 2 * c;
            uint2 a02 = *(const uint2*)&Qs[wr + g][kc];
            uint2 a13 = *(const uint2*)&Qs[wr + g + 8][kc];
            #pragma unroll
            for (int ni = 0; ni < 8; ni++) {
                uint2 b01 = *(const uint2*)&Ks[ni * 8 + g][kc];
                mma8(sc[ni], a02.x, a13.x, a02.y, a13.y, b01.x, b01.y);
            }
        }

        // Online softmax. Thread owns rows wr+g (idx 0,1) and wr+g+8 (idx 2,3).
        {
            float mx = -1e30f;
            #pragma unroll
            for (int ni = 0; ni < 8; ni++) mx = fmaxf(mx, fmaxf(sc[ni][0], sc[ni][1]));
            mx = fmaxf(mx, __shfl_xor_sync(0xffffffffu, mx, 1));
            mx = fmaxf(mx, __shfl_xor_sync(0xffffffffu, mx, 2));
            const float mn = fmaxf(m0r, mx);
            const float corr = __expf(m0r - mn);
            m0r = mn;
            float s = 0.f;
            #pragma unroll
            for (int ni = 0; ni < 8; ni++) {
                sc[ni][0] = __expf(sc[ni][0] - mn);
                sc[ni][1] = __expf(sc[ni][1] - mn);
                s += sc[ni][0] + sc[ni][1];
            }
            s += __shfl_xor_sync(0xffffffffu, s, 1);
            s += __shfl_xor_sync(0xffffffffu, s, 2);
            l0 = l0 * corr + s;
            #pragma unroll
            for (int ni = 0; ni < 8; ni++) { O[ni][0] *= corr; O[ni][1] *= corr; }
        }
        {
            float mx = -1e30f;
            #pragma unroll
            for (int ni = 0; ni < 8; ni++) mx = fmaxf(mx, fmaxf(sc[ni][2], sc[ni][3]));
            mx = fmaxf(mx, __shfl_xor_sync(0xffffffffu, mx, 1));
            mx = fmaxf(mx, __shfl_xor_sync(0xffffffffu, mx, 2));
            const float mn = fmaxf(m1r, mx);
            const float corr = __expf(m1r - mn);
            m1r = mn;
            float s = 0.f;
            #pragma unroll
            for (int ni = 0; ni < 8; ni++) {
                sc[ni][2] = __expf(sc[ni][2] - mn);
                sc[ni][3] = __expf(sc[ni][3] - mn);
                s += sc[ni][2] + sc[ni][3];
            }
            s += __shfl_xor_sync(0xffffffffu, s, 1);
            s += __shfl_xor_sync(0xffffffffu, s, 2);
            l1 = l1 * corr + s;
            #pragma unroll
            for (int ni = 0; ni < 8; ni++) { O[ni][2] *= corr; O[ni][3] *= corr; }
        }

        // Stage P with permuted columns (warp-private rows).
        {
            const int p0 = (c < 2) ? 4 * c : 4 * c - 7;
            const int p1 = (c < 2) ? 4 * c + 2 : 4 * c - 5;
            #pragma unroll
            for (int ni = 0; ni < 8; ni++) {
                Ps[wr + g][ni * 8 + p0]     = f2t(sc[ni][0]);
                Ps[wr + g][ni * 8 + p1]     = f2t(sc[ni][1]);
                Ps[wr + g + 8][ni * 8 + p0] = f2t(sc[ni][2]);
                Ps[wr + g + 8][ni * 8 + p1] = f2t(sc[ni][3]);
            }
        }
        __syncwarp();

        // O += P @ V
        #pragma unroll
        for (int d = 0; d < 8; d++) {
            const int kc = d * 8 + 2 * c;
            uint2 a02 = *(const uint2*)&Ps[wr + g][kc];
            uint2 a13 = *(const uint2*)&Ps[wr + g + 8][kc];
            #pragma unroll
            for (int ni = 0; ni < 8; ni++) {
                uint2 b01 = *(const uint2*)&Vt[ni * 8 + g][kc];
                mma8(O[ni], a02.x, a13.x, a02.y, a13.y, b01.x, b01.y);
            }
        }
    }

    // Normalize + write [B,S,D]
    const int b_ = bh >> 3, h_ = bh & 7;
    const float inv0 = 1.0f / l0, inv1 = 1.0f / l1;
    const int s0 = qt * 128 + wr + g;
    float* o0 = Out + ((size_t)(b_ * SS + s0)) * DD + h_ * 64;
    float* o1 = o0 + 8 * DD;
    #pragma unroll
    for (int ni = 0; ni < 8; ni++) {
        const int cc = ni * 8 + c * 2;
        o0[cc]     = O[ni][0] * inv0;
        o0[cc + 1] = O[ni][1] * inv0;
        o1[cc]     = O[ni][2] * inv1;
        o1[cc + 1] = O[ni][3] * inv1;
    }
}

// ---------------------------------------------------------------------------

extern "C" void kernel_launch(void* const* d_in, const int* in_sizes, int n_in,
                              void* d_out, int out_size) {
    const float* x  = (const float*)d_in[0];
    const float* Wq = (const float*)d_in[1];
    const float* bq = (const float*)d_in[2];
    const float* Wk = (const float*)d_in[3];
    const float* bk = (const float*)d_in[4];
    const float* Wv = (const float*)d_in[5];
    const float* bv = (const float*)d_in[6];
    const float* Wo = (const float*)d_in[7];
    const float* bo = (const float*)d_in[8];
    float* out = (float*)d_out;

    float *Q, *K, *V, *attn;
    cudaGetSymbolAddress((void**)&Q, g_Q);
    cudaGetSymbolAddress((void**)&K, g_K);
    cudaGetSymbolAddress((void**)&V, g_V);
    cudaGetSymbolAddress((void**)&attn, g_attn);

    const int proj_smem = (2 * 128 * PPITCH + 2 * 64 * PPITCH) * 4;   // 61440 B
    const int attn_smem = 384 * APITCH * 4;                            // 110592 B
    cudaFuncSetAttribute(qkv_proj_kernel, cudaFuncAttributeMaxDynamicSharedMemorySize, proj_smem);
    cudaFuncSetAttribute(out_proj_kernel, cudaFuncAttributeMaxDynamicSharedMemorySize, proj_smem);
    cudaFuncSetAttribute(attn_kernel,     cudaFuncAttributeMaxDynamicSharedMemorySize, attn_smem);

    qkv_proj_kernel<<<dim3(8, 32, 3), 256, proj_smem>>>(x, Wq, bq, Wk, bk, Wv, bv);
    attn_kernel<<<dim3(16, 16), 256, attn_smem>>>(Q, K, V, attn);
    out_proj_kernel<<<dim3(8, 32), 256, proj_smem>>>(Wo, bo, out);
}